// round 1
// baseline (speedup 1.0000x reference)
#include <cuda_runtime.h>
#include <cstdint>

#define M_TOTAL 16384
#define K_CODES 8192
#define DIM     512
#define BM      128
#define BN      128
#define BK      16
#define NTHREADS 256

__device__ float g_e2[K_CODES];
__device__ int   g_idx[M_TOTAL];

// Packed f32x2 FMA: d = a*b + c elementwise on two packed fp32 lanes.
// Only reachable via PTX (ptxas never auto-fuses 2x fmaf) -> 2x fp32 throughput.
__device__ __forceinline__ unsigned long long ffma2(unsigned long long a,
                                                    unsigned long long b,
                                                    unsigned long long c) {
    unsigned long long d;
    asm("fma.rn.f32x2 %0, %1, %2, %3;" : "=l"(d) : "l"(a), "l"(b), "l"(c));
    return d;
}

__device__ __forceinline__ unsigned long long dup2(float v) {
    unsigned long long r;
    asm("mov.b64 %0, {%1, %1};" : "=l"(r) : "r"(__float_as_uint(v)));
    return r;
}

// ---------------------------------------------------------------------------
// Kernel 1: e2[k] = sum_d emb[k][d]^2   (one warp per row)
// ---------------------------------------------------------------------------
__global__ void e2_kernel(const float* __restrict__ emb) {
    int row  = blockIdx.x * (blockDim.x / 32) + (threadIdx.x >> 5);
    int lane = threadIdx.x & 31;
    const float4* p = reinterpret_cast<const float4*>(emb + (size_t)row * DIM);
    float s = 0.f;
#pragma unroll
    for (int i = 0; i < DIM / 4 / 32; ++i) {   // 4 iterations
        float4 v = p[lane + i * 32];
        s += v.x * v.x + v.y * v.y + v.z * v.z + v.w * v.w;
    }
#pragma unroll
    for (int o = 16; o; o >>= 1) s += __shfl_xor_sync(0xffffffffu, s, o);
    if (lane == 0) g_e2[row] = s;
}

// ---------------------------------------------------------------------------
// Kernel 2: fused GEMM + row argmax of (x.e - e2/2).
// 128x128 CTA tile, BK=16, 256 threads, 8x8 per-thread microtile computed as
// 8 rows x 4 column-pairs with packed fma.rn.f32x2.
// A is stored in smem duplicated ({v,v} u64) so no per-step packing is needed.
// ---------------------------------------------------------------------------
__global__ __launch_bounds__(NTHREADS)
void vq_argmin_kernel(const float* __restrict__ x, const float* __restrict__ emb) {
    __shared__ unsigned long long As2[BK][BM];   // 16 KB (duplicated pairs)
    __shared__ float             Bs[BK][BN];     // 8 KB
    __shared__ float             e2s[BN];
    __shared__ float             sScore[BM][16]; // 8 KB
    __shared__ int               sIdx[BM][16];   // 8 KB

    const int tid = threadIdx.x;
    const int tx  = tid & 15;     // column group (8 cols)
    const int ty  = tid >> 4;     // row group (8 rows)
    const int m0  = blockIdx.x * BM;

    // Loader mapping: each thread loads 2 float4 for A and 2 for B per chunk.
    const int lrow = tid >> 2;          // 0..63
    const int lc4  = (tid & 3) * 4;     // d offset within 16: 0,4,8,12

    float best[8];
    int   bidx[8];
#pragma unroll
    for (int i = 0; i < 8; ++i) { best[i] = -3.4e38f; bidx[i] = 0; }

    const float* xA0 = x + (size_t)(m0 + lrow) * DIM + lc4;
    const float* xA1 = xA0 + (size_t)64 * DIM;

    for (int n0 = 0; n0 < K_CODES; n0 += BN) {
        unsigned long long acc[8][4];
#pragma unroll
        for (int i = 0; i < 8; ++i)
#pragma unroll
            for (int j = 0; j < 4; ++j) acc[i][j] = 0ull;

        if (tid < BN) e2s[tid] = g_e2[n0 + tid];

        const float* eB0 = emb + (size_t)(n0 + lrow) * DIM + lc4;
        const float* eB1 = eB0 + (size_t)64 * DIM;

        // Prefetch chunk d0=0 into registers.
        float4 ra0 = *(const float4*)(xA0);
        float4 ra1 = *(const float4*)(xA1);
        float4 rb0 = *(const float4*)(eB0);
        float4 rb1 = *(const float4*)(eB1);

        for (int d0 = 0; d0 < DIM; d0 += BK) {
            // Commit prefetched chunk to smem.
            As2[lc4 + 0][lrow]      = dup2(ra0.x);
            As2[lc4 + 1][lrow]      = dup2(ra0.y);
            As2[lc4 + 2][lrow]      = dup2(ra0.z);
            As2[lc4 + 3][lrow]      = dup2(ra0.w);
            As2[lc4 + 0][lrow + 64] = dup2(ra1.x);
            As2[lc4 + 1][lrow + 64] = dup2(ra1.y);
            As2[lc4 + 2][lrow + 64] = dup2(ra1.z);
            As2[lc4 + 3][lrow + 64] = dup2(ra1.w);
            Bs[lc4 + 0][lrow]      = rb0.x;
            Bs[lc4 + 1][lrow]      = rb0.y;
            Bs[lc4 + 2][lrow]      = rb0.z;
            Bs[lc4 + 3][lrow]      = rb0.w;
            Bs[lc4 + 0][lrow + 64] = rb1.x;
            Bs[lc4 + 1][lrow + 64] = rb1.y;
            Bs[lc4 + 2][lrow + 64] = rb1.z;
            Bs[lc4 + 3][lrow + 64] = rb1.w;
            __syncthreads();

            // Prefetch next chunk (overlaps with compute below).
            if (d0 + BK < DIM) {
                ra0 = *(const float4*)(xA0 + d0 + BK);
                ra1 = *(const float4*)(xA1 + d0 + BK);
                rb0 = *(const float4*)(eB0 + d0 + BK);
                rb1 = *(const float4*)(eB1 + d0 + BK);
            }

#pragma unroll
            for (int d = 0; d < BK; ++d) {
                ulonglong2 a01 = *(const ulonglong2*)(&As2[d][ty * 8 + 0]);
                ulonglong2 a23 = *(const ulonglong2*)(&As2[d][ty * 8 + 2]);
                ulonglong2 a45 = *(const ulonglong2*)(&As2[d][ty * 8 + 4]);
                ulonglong2 a67 = *(const ulonglong2*)(&As2[d][ty * 8 + 6]);
                ulonglong2 b01 = *(const ulonglong2*)(&Bs[d][tx * 8 + 0]);
                ulonglong2 b23 = *(const ulonglong2*)(&Bs[d][tx * 8 + 4]);
                unsigned long long ap[8] = {a01.x, a01.y, a23.x, a23.y,
                                            a45.x, a45.y, a67.x, a67.y};
                unsigned long long bp[4] = {b01.x, b01.y, b23.x, b23.y};
#pragma unroll
                for (int i = 0; i < 8; ++i) {
                    acc[i][0] = ffma2(ap[i], bp[0], acc[i][0]);
                    acc[i][1] = ffma2(ap[i], bp[1], acc[i][1]);
                    acc[i][2] = ffma2(ap[i], bp[2], acc[i][2]);
                    acc[i][3] = ffma2(ap[i], bp[3], acc[i][3]);
                }
            }
            __syncthreads();
        }

        // Epilogue: score = dot - e2/2, running argmax per row.
        // Strict '>' + ascending k order keeps the smallest index on ties.
#pragma unroll
        for (int i = 0; i < 8; ++i) {
#pragma unroll
            for (int jp = 0; jp < 4; ++jp) {
                union { unsigned long long u; float2 f; } cvt;
                cvt.u = acc[i][jp];
                int c0 = tx * 8 + jp * 2;
                float s0 = cvt.f.x - 0.5f * e2s[c0];
                float s1 = cvt.f.y - 0.5f * e2s[c0 + 1];
                if (s0 > best[i]) { best[i] = s0; bidx[i] = n0 + c0; }
                if (s1 > best[i]) { best[i] = s1; bidx[i] = n0 + c0 + 1; }
            }
        }
        __syncthreads();  // protect e2s before next tile's rewrite
    }

    // Cross-thread (tx) reduction per row.
#pragma unroll
    for (int i = 0; i < 8; ++i) {
        sScore[ty * 8 + i][tx] = best[i];
        sIdx[ty * 8 + i][tx]   = bidx[i];
    }
    __syncthreads();
    if (tid < BM) {
        float bs = sScore[tid][0];
        int   bi = sIdx[tid][0];
#pragma unroll
        for (int t = 1; t < 16; ++t) {
            float s = sScore[tid][t];
            int   ii = sIdx[tid][t];
            if (s > bs || (s == bs && ii < bi)) { bs = s; bi = ii; }
        }
        g_idx[m0 + tid] = bi;
    }
}

// ---------------------------------------------------------------------------
// Kernel 3: gather out[m] = emb[g_idx[m]]
// ---------------------------------------------------------------------------
__global__ void gather_kernel(const float* __restrict__ emb, float* __restrict__ out) {
    int row = blockIdx.x;
    int idx = g_idx[row];
    const float4* src = reinterpret_cast<const float4*>(emb + (size_t)idx * DIM);
    float4*       dst = reinterpret_cast<float4*>(out + (size_t)row * DIM);
    dst[threadIdx.x] = src[threadIdx.x];   // 128 threads * float4 = 512 floats
}

extern "C" void kernel_launch(void* const* d_in, const int* in_sizes, int n_in,
                              void* d_out, int out_size) {
    const float* x   = (const float*)d_in[0];
    const float* emb = (const float*)d_in[1];
    float*       out = (float*)d_out;

    e2_kernel<<<K_CODES / 8, 256>>>(emb);
    vq_argmin_kernel<<<M_TOTAL / BM, NTHREADS>>>(x, emb);
    gather_kernel<<<M_TOTAL, 128>>>(emb, out);
}

// round 3
// speedup vs baseline: 2.3312x; 2.3312x over previous
#include <cuda_runtime.h>
#include <cuda_bf16.h>
#include <cstdint>
#include <cfloat>

// ---------------------------------------------------------------------------
// Problem constants
// ---------------------------------------------------------------------------
#define M_TOTAL 16384
#define K_CODES 8192
#define DIM     512
#define KCAT    1536            // 3*DIM: [hh' | hm' | mh'] concatenated along K
#define MT      128             // rows per CTA
#define BN      128             // codes per chunk
#define NCHUNK  (K_CODES / BN)  // 64
#define BK      64              // bf16 K per pipeline step (128 B/row)
#define KSTEPS  (KCAT / BK)     // 24
#define STAGES  3
#define NTHR    256

// ---------------------------------------------------------------------------
// Scratch (static device arrays: allocation-free rule)
// ---------------------------------------------------------------------------
__device__ __nv_bfloat16 g_Acat[(size_t)M_TOTAL * KCAT];  // [h | h | m]
__device__ __nv_bfloat16 g_Bcat[(size_t)K_CODES * KCAT];  // [h'| m'| h']
__device__ float g_e2[K_CODES];
__device__ int   g_i1[M_TOTAL];
__device__ int   g_i2[M_TOTAL];

// ---------------------------------------------------------------------------
// Baseline-PTX helpers (no "a"-suffix arch features!)
// ---------------------------------------------------------------------------
__device__ __forceinline__ uint32_t smem_u32(const void* p) {
    uint32_t a;
    asm("{ .reg .u64 t; cvta.to.shared.u64 t, %1; cvt.u32.u64 %0, t; }"
        : "=r"(a) : "l"(p));
    return a;
}

__device__ __forceinline__ void cp_async16(uint32_t dst, const void* src) {
    uint64_t g;
    asm("cvta.to.global.u64 %0, %1;" : "=l"(g) : "l"(src));
    asm volatile("cp.async.cg.shared.global [%0], [%1], 16;"
                 :: "r"(dst), "l"(g) : "memory");
}
#define CP_COMMIT() asm volatile("cp.async.commit_group;" ::: "memory")

__device__ __forceinline__ void ldmatrix_x4(uint32_t& r0, uint32_t& r1,
                                            uint32_t& r2, uint32_t& r3,
                                            uint32_t addr) {
    asm volatile("ldmatrix.sync.aligned.m8n8.x4.shared.b16 {%0,%1,%2,%3}, [%4];"
                 : "=r"(r0), "=r"(r1), "=r"(r2), "=r"(r3) : "r"(addr));
}

__device__ __forceinline__ void mma_bf16(float& d0, float& d1, float& d2, float& d3,
                                         uint32_t a0, uint32_t a1, uint32_t a2, uint32_t a3,
                                         uint32_t b0, uint32_t b1) {
    asm volatile(
        "mma.sync.aligned.m16n8k16.row.col.f32.bf16.bf16.f32 "
        "{%0,%1,%2,%3}, {%4,%5,%6,%7}, {%8,%9}, {%0,%1,%2,%3};"
        : "+f"(d0), "+f"(d1), "+f"(d2), "+f"(d3)
        : "r"(a0), "r"(a1), "r"(a2), "r"(a3), "r"(b0), "r"(b1));
}

// ---------------------------------------------------------------------------
// SMEM layout (dynamic)
// ---------------------------------------------------------------------------
#define SM_E2      0            // 128 floats
#define SM_MBUF    1024         // 128 rows x 4 warps x float4 = 8 KB
#define SM_A       16384        // STAGES x 16 KB
#define A_STAGE    16384
#define SM_B       (SM_A + STAGES * A_STAGE)   // 65536, STAGES x 16 KB
#define B_STAGE    16384
#define SMEM_TOTAL (SM_B + STAGES * B_STAGE)   // 114688

// ---------------------------------------------------------------------------
// Kernel 1: e2[k] = ||emb_k||^2 (exact fp32)
// ---------------------------------------------------------------------------
__global__ void e2_kernel(const float* __restrict__ emb) {
    int row  = blockIdx.x * 8 + (threadIdx.x >> 5);
    int lane = threadIdx.x & 31;
    const float4* p = reinterpret_cast<const float4*>(emb + (size_t)row * DIM);
    float s = 0.f;
#pragma unroll
    for (int i = 0; i < 4; ++i) {
        float4 v = p[lane + i * 32];
        s += v.x * v.x + v.y * v.y + v.z * v.z + v.w * v.w;
    }
#pragma unroll
    for (int o = 16; o; o >>= 1) s += __shfl_xor_sync(0xffffffffu, s, o);
    if (lane == 0) g_e2[row] = s;
}

// ---------------------------------------------------------------------------
// Split kernels: A_cat = [h|h|m], B_cat = [h'|m'|h']
// ---------------------------------------------------------------------------
__global__ void split_x_kernel(const float* __restrict__ x) {
    int i = blockIdx.x * 256 + threadIdx.x;
    int row = i >> 9, col = i & 511;
    float v = x[i];
    __nv_bfloat16 h = __float2bfloat16(v);
    __nv_bfloat16 m = __float2bfloat16(v - __bfloat162float(h));
    __nv_bfloat16* A = g_Acat + (size_t)row * KCAT;
    A[col] = h; A[512 + col] = h; A[1024 + col] = m;
}

__global__ void split_e_kernel(const float* __restrict__ emb) {
    int i = blockIdx.x * 256 + threadIdx.x;
    int row = i >> 9, col = i & 511;
    float v = emb[i];
    __nv_bfloat16 h = __float2bfloat16(v);
    __nv_bfloat16 m = __float2bfloat16(v - __bfloat162float(h));
    __nv_bfloat16* B = g_Bcat + (size_t)row * KCAT;
    B[col] = h; B[512 + col] = m; B[1024 + col] = h;
}

// ---------------------------------------------------------------------------
// Main kernel: HMMA GEMM + fused per-row top-2 argmax
// ---------------------------------------------------------------------------
__device__ __forceinline__ void fill_stage(uint32_t sb, int stage, int step,
                                           int m0, int n0, int tid) {
    const int gk = step * BK;
    uint32_t ab = sb + SM_A + stage * A_STAGE;
#pragma unroll
    for (int j = 0; j < 4; ++j) {
        int id = tid + j * 256;          // 1024 16B-chunks: 128 rows x 8
        int row = id >> 3, c = id & 7;
        const void* src = g_Acat + (size_t)(m0 + row) * KCAT + gk + c * 8;
        cp_async16(ab + row * 128 + ((c ^ (row & 7)) * 16), src);
    }
    uint32_t bb = sb + SM_B + stage * B_STAGE;
#pragma unroll
    for (int j = 0; j < 4; ++j) {
        int id = tid + j * 256;
        int row = id >> 3, c = id & 7;
        const void* src = g_Bcat + (size_t)(n0 + row) * KCAT + gk + c * 8;
        cp_async16(bb + row * 128 + ((c ^ (row & 7)) * 16), src);
    }
    CP_COMMIT();
}

__device__ __forceinline__ void top2_upd(float& b1, int& i1, float& b2, int& i2,
                                         float s, int idx) {
    if (s > b1 || (s == b1 && idx < i1)) { b2 = b1; i2 = i1; b1 = s; i1 = idx; }
    else if (s > b2 || (s == b2 && idx < i2)) { b2 = s; i2 = idx; }
}

__global__ void __launch_bounds__(NTHR, 1)
vq_main_kernel() {
    extern __shared__ char smem[];
    uint32_t sb = smem_u32(smem);
    float* e2s  = reinterpret_cast<float*>(smem + SM_E2);
    float4* mbuf = reinterpret_cast<float4*>(smem + SM_MBUF);

    const int tid  = threadIdx.x;
    const int lane = tid & 31;
    const int wid  = tid >> 5;
    const int wm   = wid >> 2;     // 0..1 (m half: 64 rows)
    const int wn   = wid & 3;      // 0..3 (n quarter: 32 cols)
    const int m0   = blockIdx.x * MT;

    float rb1 = -FLT_MAX, rb2 = -FLT_MAX;
    int   ri1 = 0x7fffffff, ri2 = 0x7fffffff;

#pragma unroll 1
    for (int ch = 0; ch < NCHUNK; ++ch) {
        const int n0 = ch * BN;
        if (tid < BN) e2s[tid] = g_e2[n0 + tid];

        float acc[4][4][4];
#pragma unroll
        for (int a = 0; a < 4; ++a)
#pragma unroll
            for (int b = 0; b < 4; ++b)
#pragma unroll
                for (int c = 0; c < 4; ++c) acc[a][b][c] = 0.f;

        fill_stage(sb, 0, 0, m0, n0, tid);
        fill_stage(sb, 1, 1, m0, n0, tid);

#pragma unroll 1
        for (int st = 0; st < KSTEPS; ++st) {
            if (st < KSTEPS - 1) asm volatile("cp.async.wait_group 1;" ::: "memory");
            else                 asm volatile("cp.async.wait_group 0;" ::: "memory");
            __syncthreads();
            if (st + 2 < KSTEPS) fill_stage(sb, (st + 2) % STAGES, st + 2, m0, n0, tid);

            const int stg = st % STAGES;
            const uint32_t ab = sb + SM_A + stg * A_STAGE;
            const uint32_t bb = sb + SM_B + stg * B_STAGE;

#pragma unroll
            for (int sub = 0; sub < 4; ++sub) {   // 4 x k16 per BK=64 step
                // ---- B fragments: 4 n-frags (8 cols each) = 2 ldmatrix.x4 ----
                uint32_t bfr[4][2];
#pragma unroll
                for (int p = 0; p < 2; ++p) {
                    int mi   = lane >> 3;          // 0..3
                    int noff = (mi >> 1) * 8;
                    int kc   = mi & 1;
                    int row  = wn * 32 + p * 16 + noff + (lane & 7);
                    int c    = sub * 2 + kc;
                    uint32_t addr = bb + row * 128 + ((c ^ (row & 7)) * 16);
                    ldmatrix_x4(bfr[p*2][0], bfr[p*2][1],
                                bfr[p*2+1][0], bfr[p*2+1][1], addr);
                }
                // ---- A fragments + MMAs, one m-frag at a time ----
#pragma unroll
                for (int mf = 0; mf < 4; ++mf) {
                    int row = wm * 64 + mf * 16 + (lane & 15);
                    int c   = sub * 2 + (lane >> 4);
                    uint32_t addr = ab + row * 128 + ((c ^ (row & 7)) * 16);
                    uint32_t a0, a1, a2, a3;
                    ldmatrix_x4(a0, a1, a2, a3, addr);
#pragma unroll
                    for (int nf = 0; nf < 4; ++nf)
                        mma_bf16(acc[mf][nf][0], acc[mf][nf][1],
                                 acc[mf][nf][2], acc[mf][nf][3],
                                 a0, a1, a2, a3, bfr[nf][0], bfr[nf][1]);
                }
            }
        }
        __syncthreads();   // all HMMA reads done; also orders e2s for reading

        // ---- epilogue: per-row top-2 over this chunk's 128 cols ----
        const int q = lane & 3;                    // col pair within frag
#pragma unroll
        for (int mf = 0; mf < 4; ++mf) {
#pragma unroll
            for (int h = 0; h < 2; ++h) {          // row half of the 16x8 frag
                float tb1 = -FLT_MAX, tb2 = -FLT_MAX;
                int   ti1 = 0x7fffffff, ti2 = 0x7fffffff;
#pragma unroll
                for (int nf = 0; nf < 4; ++nf) {
                    int cloc = wn * 32 + nf * 8 + q * 2;
                    float s0 = acc[mf][nf][h*2+0] - 0.5f * e2s[cloc];
                    float s1 = acc[mf][nf][h*2+1] - 0.5f * e2s[cloc+1];
                    top2_upd(tb1, ti1, tb2, ti2, s0, n0 + cloc);
                    top2_upd(tb1, ti1, tb2, ti2, s1, n0 + cloc + 1);
                }
                // quad merge (lanes differing in bits 0,1 share the row)
#pragma unroll
                for (int o = 1; o <= 2; o <<= 1) {
                    float ob1 = __shfl_xor_sync(0xffffffffu, tb1, o);
                    float ob2 = __shfl_xor_sync(0xffffffffu, tb2, o);
                    int   oi1 = __shfl_xor_sync(0xffffffffu, ti1, o);
                    int   oi2 = __shfl_xor_sync(0xffffffffu, ti2, o);
                    top2_upd(tb1, ti1, tb2, ti2, ob1, oi1);
                    top2_upd(tb1, ti1, tb2, ti2, ob2, oi2);
                }
                if (q == 0) {
                    int row_local = wm * 64 + mf * 16 + h * 8 + (lane >> 2);
                    mbuf[row_local * 4 + wn] =
                        make_float4(tb1, tb2, __int_as_float(ti1), __int_as_float(ti2));
                }
            }
        }
        __syncthreads();
        if (tid < MT) {
#pragma unroll
            for (int w = 0; w < 4; ++w) {
                float4 v = mbuf[tid * 4 + w];
                top2_upd(rb1, ri1, rb2, ri2, v.x, __float_as_int(v.z));
                top2_upd(rb1, ri1, rb2, ri2, v.y, __float_as_int(v.w));
            }
        }
        __syncthreads();
    }

    if (tid < MT) { g_i1[m0 + tid] = ri1; g_i2[m0 + tid] = ri2; }
}

// ---------------------------------------------------------------------------
// Refine + gather: exact fp32 re-score of top-2, copy the winner row.
// ---------------------------------------------------------------------------
__global__ void refine_gather_kernel(const float* __restrict__ x,
                                     const float* __restrict__ emb,
                                     float* __restrict__ out) {
    int row  = (blockIdx.x * blockDim.x + threadIdx.x) >> 5;
    int lane = threadIdx.x & 31;
    int i1 = g_i1[row], i2 = g_i2[row];

    const float4* xr = reinterpret_cast<const float4*>(x + (size_t)row * DIM);
    const float4* e1 = reinterpret_cast<const float4*>(emb + (size_t)i1 * DIM);
    const float4* e2 = reinterpret_cast<const float4*>(emb + (size_t)i2 * DIM);
    float d1 = 0.f, d2 = 0.f;
#pragma unroll
    for (int j = 0; j < 4; ++j) {
        float4 xv = xr[lane + j * 32];
        float4 a  = e1[lane + j * 32];
        float4 b  = e2[lane + j * 32];
        d1 += xv.x * a.x + xv.y * a.y + xv.z * a.z + xv.w * a.w;
        d2 += xv.x * b.x + xv.y * b.y + xv.z * b.z + xv.w * b.w;
    }
#pragma unroll
    for (int o = 16; o; o >>= 1) {
        d1 += __shfl_xor_sync(0xffffffffu, d1, o);
        d2 += __shfl_xor_sync(0xffffffffu, d2, o);
    }
    float s1 = d1 - 0.5f * g_e2[i1];
    float s2 = d2 - 0.5f * g_e2[i2];
    int best = (s2 > s1 || (s2 == s1 && i2 < i1)) ? i2 : i1;

    const float4* src = reinterpret_cast<const float4*>(emb + (size_t)best * DIM);
    float4*       dst = reinterpret_cast<float4*>(out + (size_t)row * DIM);
#pragma unroll
    for (int j = 0; j < 4; ++j) dst[lane + j * 32] = src[lane + j * 32];
}

// ---------------------------------------------------------------------------
extern "C" void kernel_launch(void* const* d_in, const int* in_sizes, int n_in,
                              void* d_out, int out_size) {
    const float* x   = (const float*)d_in[0];
    const float* emb = (const float*)d_in[1];
    float*       out = (float*)d_out;

    cudaFuncSetAttribute(vq_main_kernel,
                         cudaFuncAttributeMaxDynamicSharedMemorySize, SMEM_TOTAL);

    e2_kernel<<<K_CODES / 8, 256>>>(emb);
    split_x_kernel<<<(M_TOTAL * DIM) / 256, 256>>>(x);
    split_e_kernel<<<(K_CODES * DIM) / 256, 256>>>(emb);
    vq_main_kernel<<<M_TOTAL / MT, NTHR, SMEM_TOTAL>>>();
    refine_gather_kernel<<<M_TOTAL / 8, 256>>>(x, emb, out);
}

// round 4
// speedup vs baseline: 2.7982x; 1.2003x over previous
#include <cuda_runtime.h>
#include <cuda_bf16.h>
#include <cstdint>
#include <cfloat>

// ---------------------------------------------------------------------------
// Problem constants
// ---------------------------------------------------------------------------
#define M_TOTAL 16384
#define K_CODES 8192
#define DIM     512
#define KCAT    1536            // 3*DIM: [hh' | hm' | mh'] concatenated along K
#define MT      64              // rows per CTA (2 CTAs/SM)
#define BN      128             // codes per chunk
#define NCHUNK  (K_CODES / BN)  // 64
#define BK      64              // bf16 K per pipeline step (128 B/row)
#define KSTEPS  (KCAT / BK)     // 24
#define STAGES  4
#define NTHR    256

// ---------------------------------------------------------------------------
// Scratch (static device arrays: allocation-free rule)
// ---------------------------------------------------------------------------
__device__ __nv_bfloat16 g_Acat[(size_t)M_TOTAL * KCAT];  // [h | h | m]
__device__ __nv_bfloat16 g_Bcat[(size_t)K_CODES * KCAT];  // [h'| m'| h']
__device__ float g_e2[K_CODES];
__device__ int   g_i1[M_TOTAL];
__device__ int   g_i2[M_TOTAL];

// ---------------------------------------------------------------------------
// Baseline-PTX helpers (no "a"-suffix arch features)
// ---------------------------------------------------------------------------
__device__ __forceinline__ uint32_t smem_u32(const void* p) {
    uint32_t a;
    asm("{ .reg .u64 t; cvta.to.shared.u64 t, %1; cvt.u32.u64 %0, t; }"
        : "=r"(a) : "l"(p));
    return a;
}

__device__ __forceinline__ void cp_async16(uint32_t dst, const void* src) {
    uint64_t g;
    asm("cvta.to.global.u64 %0, %1;" : "=l"(g) : "l"(src));
    asm volatile("cp.async.cg.shared.global [%0], [%1], 16;"
                 :: "r"(dst), "l"(g) : "memory");
}
#define CP_COMMIT() asm volatile("cp.async.commit_group;" ::: "memory")

__device__ __forceinline__ void ldmatrix_x4(uint32_t& r0, uint32_t& r1,
                                            uint32_t& r2, uint32_t& r3,
                                            uint32_t addr) {
    asm volatile("ldmatrix.sync.aligned.m8n8.x4.shared.b16 {%0,%1,%2,%3}, [%4];"
                 : "=r"(r0), "=r"(r1), "=r"(r2), "=r"(r3) : "r"(addr));
}

__device__ __forceinline__ void mma_bf16(float& d0, float& d1, float& d2, float& d3,
                                         uint32_t a0, uint32_t a1, uint32_t a2, uint32_t a3,
                                         uint32_t b0, uint32_t b1) {
    asm volatile(
        "mma.sync.aligned.m16n8k16.row.col.f32.bf16.bf16.f32 "
        "{%0,%1,%2,%3}, {%4,%5,%6,%7}, {%8,%9}, {%0,%1,%2,%3};"
        : "+f"(d0), "+f"(d1), "+f"(d2), "+f"(d3)
        : "r"(a0), "r"(a1), "r"(a2), "r"(a3), "r"(b0), "r"(b1));
}

// ---------------------------------------------------------------------------
// SMEM layout (dynamic): 104 KB per CTA -> 2 CTAs/SM (208 KB of 228 KB)
// ---------------------------------------------------------------------------
#define SM_E2      0                         // 128 floats
#define SM_MBUF    1024                      // 64 rows x 4 warps x float4 = 4 KB
#define SM_A       8192                      // STAGES x 8 KB  (64 rows x 128 B)
#define A_STAGE    8192
#define SM_B       (SM_A + STAGES * A_STAGE) // 40960, STAGES x 16 KB (128 x 128 B)
#define B_STAGE    16384
#define SMEM_TOTAL (SM_B + STAGES * B_STAGE) // 106496

// ---------------------------------------------------------------------------
// Kernel 1: e2[k] = ||emb_k||^2 (exact fp32)
// ---------------------------------------------------------------------------
__global__ void e2_kernel(const float* __restrict__ emb) {
    int row  = blockIdx.x * 8 + (threadIdx.x >> 5);
    int lane = threadIdx.x & 31;
    const float4* p = reinterpret_cast<const float4*>(emb + (size_t)row * DIM);
    float s = 0.f;
#pragma unroll
    for (int i = 0; i < 4; ++i) {
        float4 v = p[lane + i * 32];
        s += v.x * v.x + v.y * v.y + v.z * v.z + v.w * v.w;
    }
#pragma unroll
    for (int o = 16; o; o >>= 1) s += __shfl_xor_sync(0xffffffffu, s, o);
    if (lane == 0) g_e2[row] = s;
}

// ---------------------------------------------------------------------------
// Split kernels: A_cat = [h|h|m], B_cat = [h'|m'|h']
// ---------------------------------------------------------------------------
__global__ void split_x_kernel(const float* __restrict__ x) {
    int i = blockIdx.x * 256 + threadIdx.x;
    int row = i >> 9, col = i & 511;
    float v = x[i];
    __nv_bfloat16 h = __float2bfloat16(v);
    __nv_bfloat16 m = __float2bfloat16(v - __bfloat162float(h));
    __nv_bfloat16* A = g_Acat + (size_t)row * KCAT;
    A[col] = h; A[512 + col] = h; A[1024 + col] = m;
}

__global__ void split_e_kernel(const float* __restrict__ emb) {
    int i = blockIdx.x * 256 + threadIdx.x;
    int row = i >> 9, col = i & 511;
    float v = emb[i];
    __nv_bfloat16 h = __float2bfloat16(v);
    __nv_bfloat16 m = __float2bfloat16(v - __bfloat162float(h));
    __nv_bfloat16* B = g_Bcat + (size_t)row * KCAT;
    B[col] = h; B[512 + col] = m; B[1024 + col] = h;
}

// ---------------------------------------------------------------------------
// Main kernel: HMMA GEMM + fused per-row top-2 argmax
// ---------------------------------------------------------------------------
__device__ __forceinline__ void fill_stage(uint32_t sb, int stage, int step,
                                           int m0, int n0, int tid) {
    const int gk = step * BK;
    uint32_t ab = sb + SM_A + stage * A_STAGE;
#pragma unroll
    for (int j = 0; j < 2; ++j) {            // A: 64 rows x 8 chunks = 512
        int id = tid + j * 256;
        int row = id >> 3, c = id & 7;
        const void* src = g_Acat + (size_t)(m0 + row) * KCAT + gk + c * 8;
        cp_async16(ab + row * 128 + ((c ^ (row & 7)) * 16), src);
    }
    uint32_t bb = sb + SM_B + stage * B_STAGE;
#pragma unroll
    for (int j = 0; j < 4; ++j) {            // B: 128 rows x 8 chunks = 1024
        int id = tid + j * 256;
        int row = id >> 3, c = id & 7;
        const void* src = g_Bcat + (size_t)(n0 + row) * KCAT + gk + c * 8;
        cp_async16(bb + row * 128 + ((c ^ (row & 7)) * 16), src);
    }
    CP_COMMIT();
}

__device__ __forceinline__ void top2_upd(float& b1, int& i1, float& b2, int& i2,
                                         float s, int idx) {
    if (s > b1 || (s == b1 && idx < i1)) { b2 = b1; i2 = i1; b1 = s; i1 = idx; }
    else if (s > b2 || (s == b2 && idx < i2)) { b2 = s; i2 = idx; }
}

__global__ void __launch_bounds__(NTHR, 2)
vq_main_kernel() {
    extern __shared__ char smem[];
    uint32_t sb = smem_u32(smem);
    float*  e2s  = reinterpret_cast<float*>(smem + SM_E2);
    float4* mbuf = reinterpret_cast<float4*>(smem + SM_MBUF);

    const int tid  = threadIdx.x;
    const int lane = tid & 31;
    const int wid  = tid >> 5;
    const int wm   = wid >> 2;     // 0..1 (m half: 32 rows)
    const int wn   = wid & 3;      // 0..3 (n quarter: 32 cols)
    const int m0   = blockIdx.x * MT;

    float rb1 = -FLT_MAX, rb2 = -FLT_MAX;
    int   ri1 = 0x7fffffff, ri2 = 0x7fffffff;

#pragma unroll 1
    for (int ch = 0; ch < NCHUNK; ++ch) {
        const int n0 = ch * BN;
        if (tid < BN) e2s[tid] = g_e2[n0 + tid];

        float acc[2][4][4];
#pragma unroll
        for (int a = 0; a < 2; ++a)
#pragma unroll
            for (int b = 0; b < 4; ++b)
#pragma unroll
                for (int c = 0; c < 4; ++c) acc[a][b][c] = 0.f;

        fill_stage(sb, 0, 0, m0, n0, tid);
        fill_stage(sb, 1, 1, m0, n0, tid);
        fill_stage(sb, 2, 2, m0, n0, tid);

#pragma unroll 1
        for (int st = 0; st < KSTEPS; ++st) {
            if (st < KSTEPS - 2)
                asm volatile("cp.async.wait_group 2;" ::: "memory");
            else if (st == KSTEPS - 2)
                asm volatile("cp.async.wait_group 1;" ::: "memory");
            else
                asm volatile("cp.async.wait_group 0;" ::: "memory");
            __syncthreads();
            if (st + 3 < KSTEPS) fill_stage(sb, (st + 3) % STAGES, st + 3, m0, n0, tid);

            const int stg = st % STAGES;
            const uint32_t ab = sb + SM_A + stg * A_STAGE;
            const uint32_t bb = sb + SM_B + stg * B_STAGE;

#pragma unroll
            for (int sub = 0; sub < 4; ++sub) {   // 4 x k16 per BK=64 step
                // ---- B fragments: 4 n-frags (8 cols each) = 2 ldmatrix.x4 ----
                uint32_t bfr[4][2];
#pragma unroll
                for (int p = 0; p < 2; ++p) {
                    int mi   = lane >> 3;          // 0..3
                    int noff = (mi >> 1) * 8;
                    int kc   = mi & 1;
                    int row  = wn * 32 + p * 16 + noff + (lane & 7);
                    int c    = sub * 2 + kc;
                    uint32_t addr = bb + row * 128 + ((c ^ (row & 7)) * 16);
                    ldmatrix_x4(bfr[p*2][0], bfr[p*2][1],
                                bfr[p*2+1][0], bfr[p*2+1][1], addr);
                }
                // ---- A fragments + MMAs ----
#pragma unroll
                for (int mf = 0; mf < 2; ++mf) {
                    int row = wm * 32 + mf * 16 + (lane & 15);
                    int c   = sub * 2 + (lane >> 4);
                    uint32_t addr = ab + row * 128 + ((c ^ (row & 7)) * 16);
                    uint32_t a0, a1, a2, a3;
                    ldmatrix_x4(a0, a1, a2, a3, addr);
#pragma unroll
                    for (int nf = 0; nf < 4; ++nf)
                        mma_bf16(acc[mf][nf][0], acc[mf][nf][1],
                                 acc[mf][nf][2], acc[mf][nf][3],
                                 a0, a1, a2, a3, bfr[nf][0], bfr[nf][1]);
                }
            }
        }
        __syncthreads();   // all HMMA smem reads done; e2s visible

        // ---- epilogue: per-row top-2 over this chunk's 128 cols ----
        const int q = lane & 3;                    // col pair within frag
#pragma unroll
        for (int mf = 0; mf < 2; ++mf) {
#pragma unroll
            for (int h = 0; h < 2; ++h) {          // row half of the 16x8 frag
                float tb1 = -FLT_MAX, tb2 = -FLT_MAX;
                int   ti1 = 0x7fffffff, ti2 = 0x7fffffff;
#pragma unroll
                for (int nf = 0; nf < 4; ++nf) {
                    int cloc = wn * 32 + nf * 8 + q * 2;
                    float s0 = acc[mf][nf][h*2+0] - 0.5f * e2s[cloc];
                    float s1 = acc[mf][nf][h*2+1] - 0.5f * e2s[cloc+1];
                    top2_upd(tb1, ti1, tb2, ti2, s0, n0 + cloc);
                    top2_upd(tb1, ti1, tb2, ti2, s1, n0 + cloc + 1);
                }
                // quad merge (lanes differing in bits 0,1 share the row)
#pragma unroll
                for (int o = 1; o <= 2; o <<= 1) {
                    float ob1 = __shfl_xor_sync(0xffffffffu, tb1, o);
                    float ob2 = __shfl_xor_sync(0xffffffffu, tb2, o);
                    int   oi1 = __shfl_xor_sync(0xffffffffu, ti1, o);
                    int   oi2 = __shfl_xor_sync(0xffffffffu, ti2, o);
                    top2_upd(tb1, ti1, tb2, ti2, ob1, oi1);
                    top2_upd(tb1, ti1, tb2, ti2, ob2, oi2);
                }
                if (q == 0) {
                    int row_local = wm * 32 + mf * 16 + h * 8 + (lane >> 2);
                    mbuf[row_local * 4 + wn] =
                        make_float4(tb1, tb2, __int_as_float(ti1), __int_as_float(ti2));
                }
            }
        }
        __syncthreads();
        if (tid < MT) {
#pragma unroll
            for (int w = 0; w < 4; ++w) {
                float4 v = mbuf[tid * 4 + w];
                top2_upd(rb1, ri1, rb2, ri2, v.x, __float_as_int(v.z));
                top2_upd(rb1, ri1, rb2, ri2, v.y, __float_as_int(v.w));
            }
        }
        __syncthreads();   // protect e2s/mbuf before next chunk rewrites
    }

    if (tid < MT) { g_i1[m0 + tid] = ri1; g_i2[m0 + tid] = ri2; }
}

// ---------------------------------------------------------------------------
// Refine + gather: exact fp32 re-score of top-2, copy the winner row.
// ---------------------------------------------------------------------------
__global__ void refine_gather_kernel(const float* __restrict__ x,
                                     const float* __restrict__ emb,
                                     float* __restrict__ out) {
    int row  = (blockIdx.x * blockDim.x + threadIdx.x) >> 5;
    int lane = threadIdx.x & 31;
    int i1 = g_i1[row], i2 = g_i2[row];

    const float4* xr = reinterpret_cast<const float4*>(x + (size_t)row * DIM);
    const float4* e1 = reinterpret_cast<const float4*>(emb + (size_t)i1 * DIM);
    const float4* e2 = reinterpret_cast<const float4*>(emb + (size_t)i2 * DIM);
    float d1 = 0.f, d2 = 0.f;
#pragma unroll
    for (int j = 0; j < 4; ++j) {
        float4 xv = xr[lane + j * 32];
        float4 a  = e1[lane + j * 32];
        float4 b  = e2[lane + j * 32];
        d1 += xv.x * a.x + xv.y * a.y + xv.z * a.z + xv.w * a.w;
        d2 += xv.x * b.x + xv.y * b.y + xv.z * b.z + xv.w * b.w;
    }
#pragma unroll
    for (int o = 16; o; o >>= 1) {
        d1 += __shfl_xor_sync(0xffffffffu, d1, o);
        d2 += __shfl_xor_sync(0xffffffffu, d2, o);
    }
    float s1 = d1 - 0.5f * g_e2[i1];
    float s2 = d2 - 0.5f * g_e2[i2];
    int best = (s2 > s1 || (s2 == s1 && i2 < i1)) ? i2 : i1;

    const float4* src = reinterpret_cast<const float4*>(emb + (size_t)best * DIM);
    float4*       dst = reinterpret_cast<float4*>(out + (size_t)row * DIM);
#pragma unroll
    for (int j = 0; j < 4; ++j) dst[lane + j * 32] = src[lane + j * 32];
}

// ---------------------------------------------------------------------------
extern "C" void kernel_launch(void* const* d_in, const int* in_sizes, int n_in,
                              void* d_out, int out_size) {
    const float* x   = (const float*)d_in[0];
    const float* emb = (const float*)d_in[1];
    float*       out = (float*)d_out;

    cudaFuncSetAttribute(vq_main_kernel,
                         cudaFuncAttributeMaxDynamicSharedMemorySize, SMEM_TOTAL);

    e2_kernel<<<K_CODES / 8, 256>>>(emb);
    split_x_kernel<<<(M_TOTAL * DIM) / 256, 256>>>(x);
    split_e_kernel<<<(K_CODES * DIM) / 256, 256>>>(emb);
    vq_main_kernel<<<M_TOTAL / MT, NTHR, SMEM_TOTAL>>>();
    refine_gather_kernel<<<M_TOTAL / 8, 256>>>(x, emb, out);
}

// round 5
// speedup vs baseline: 2.9546x; 1.0559x over previous
#include <cuda_runtime.h>
#include <cuda_bf16.h>
#include <cstdint>
#include <cfloat>

// ---------------------------------------------------------------------------
// Problem constants
// ---------------------------------------------------------------------------
#define M_TOTAL 16384
#define K_CODES 8192
#define DIM     512
#define KCAT    1536            // 3*DIM: [hh' | hm' | mh'] concatenated along K
#define MT      64              // rows per CTA (2 CTAs/SM)
#define BN      128             // codes per chunk
#define NCHUNK  (K_CODES / BN)  // 64
#define BK      128             // bf16 K per pipeline step (256 B/row)
#define KSTEPS  (KCAT / BK)     // 12
#define STAGES  2
#define NTHR    256

// ---------------------------------------------------------------------------
// Scratch (static device arrays: allocation-free rule)
// ---------------------------------------------------------------------------
__device__ __nv_bfloat16 g_Acat[(size_t)M_TOTAL * KCAT];  // [h | h | m]
__device__ __nv_bfloat16 g_Bcat[(size_t)K_CODES * KCAT];  // [h'| m'| h']
__device__ float g_e2[K_CODES];
__device__ int   g_i1[M_TOTAL];
__device__ int   g_i2[M_TOTAL];

// ---------------------------------------------------------------------------
// Baseline-PTX helpers (no "a"-suffix arch features)
// ---------------------------------------------------------------------------
__device__ __forceinline__ uint32_t smem_u32(const void* p) {
    uint32_t a;
    asm("{ .reg .u64 t; cvta.to.shared.u64 t, %1; cvt.u32.u64 %0, t; }"
        : "=r"(a) : "l"(p));
    return a;
}

__device__ __forceinline__ void cp_async16(uint32_t dst, const void* src) {
    uint64_t g;
    asm("cvta.to.global.u64 %0, %1;" : "=l"(g) : "l"(src));
    asm volatile("cp.async.cg.shared.global [%0], [%1], 16;"
                 :: "r"(dst), "l"(g) : "memory");
}
#define CP_COMMIT() asm volatile("cp.async.commit_group;" ::: "memory")

__device__ __forceinline__ void ldmatrix_x4(uint32_t& r0, uint32_t& r1,
                                            uint32_t& r2, uint32_t& r3,
                                            uint32_t addr) {
    asm volatile("ldmatrix.sync.aligned.m8n8.x4.shared.b16 {%0,%1,%2,%3}, [%4];"
                 : "=r"(r0), "=r"(r1), "=r"(r2), "=r"(r3) : "r"(addr));
}

__device__ __forceinline__ void mma_bf16(float& d0, float& d1, float& d2, float& d3,
                                         uint32_t a0, uint32_t a1, uint32_t a2, uint32_t a3,
                                         uint32_t b0, uint32_t b1) {
    asm volatile(
        "mma.sync.aligned.m16n8k16.row.col.f32.bf16.bf16.f32 "
        "{%0,%1,%2,%3}, {%4,%5,%6,%7}, {%8,%9}, {%0,%1,%2,%3};"
        : "+f"(d0), "+f"(d1), "+f"(d2), "+f"(d3)
        : "r"(a0), "r"(a1), "r"(a2), "r"(a3), "r"(b0), "r"(b1));
}

// 256 B rows: 16 x 16B chunks; XOR-swizzle within each 128B half.
__device__ __forceinline__ uint32_t swz16(int c, int row) {
    return (uint32_t)((((c ^ (row & 7)) & 7) | (c & 8)) * 16);
}

// ---------------------------------------------------------------------------
// SMEM layout (dynamic): 104 KB per CTA -> 2 CTAs/SM
// ---------------------------------------------------------------------------
#define SM_E2      0                         // 128 floats
#define SM_MBUF    1024                      // 64 rows x 4 warps x float4 = 4 KB
#define SM_A       8192                      // STAGES x 16 KB (64 rows x 256 B)
#define A_STAGE    16384
#define SM_B       (SM_A + STAGES * A_STAGE) // 40960, STAGES x 32 KB (128 x 256 B)
#define B_STAGE    32768
#define SMEM_TOTAL (SM_B + STAGES * B_STAGE) // 106496

// ---------------------------------------------------------------------------
// Kernel 1: e2[k] = ||emb_k||^2 (exact fp32)
// ---------------------------------------------------------------------------
__global__ void e2_kernel(const float* __restrict__ emb) {
    int row  = blockIdx.x * 8 + (threadIdx.x >> 5);
    int lane = threadIdx.x & 31;
    const float4* p = reinterpret_cast<const float4*>(emb + (size_t)row * DIM);
    float s = 0.f;
#pragma unroll
    for (int i = 0; i < 4; ++i) {
        float4 v = p[lane + i * 32];
        s += v.x * v.x + v.y * v.y + v.z * v.z + v.w * v.w;
    }
#pragma unroll
    for (int o = 16; o; o >>= 1) s += __shfl_xor_sync(0xffffffffu, s, o);
    if (lane == 0) g_e2[row] = s;
}

// ---------------------------------------------------------------------------
// Split kernels: A_cat = [h|h|m], B_cat = [h'|m'|h']
// ---------------------------------------------------------------------------
__global__ void split_x_kernel(const float* __restrict__ x) {
    int i = blockIdx.x * 256 + threadIdx.x;
    int row = i >> 9, col = i & 511;
    float v = x[i];
    __nv_bfloat16 h = __float2bfloat16(v);
    __nv_bfloat16 m = __float2bfloat16(v - __bfloat162float(h));
    __nv_bfloat16* A = g_Acat + (size_t)row * KCAT;
    A[col] = h; A[512 + col] = h; A[1024 + col] = m;
}

__global__ void split_e_kernel(const float* __restrict__ emb) {
    int i = blockIdx.x * 256 + threadIdx.x;
    int row = i >> 9, col = i & 511;
    float v = emb[i];
    __nv_bfloat16 h = __float2bfloat16(v);
    __nv_bfloat16 m = __float2bfloat16(v - __bfloat162float(h));
    __nv_bfloat16* B = g_Bcat + (size_t)row * KCAT;
    B[col] = h; B[512 + col] = m; B[1024 + col] = h;
}

// ---------------------------------------------------------------------------
// Main kernel: HMMA GEMM + fused per-row top-2 argmax
// ---------------------------------------------------------------------------
__device__ __forceinline__ void fill_stage(uint32_t sb, int stage, int step,
                                           int m0, int n0, int tid) {
    const int gk = step * BK;
    uint32_t ab = sb + SM_A + stage * A_STAGE;
#pragma unroll
    for (int j = 0; j < 4; ++j) {            // A: 64 rows x 16 chunks = 1024
        int id = tid + j * 256;
        int row = id >> 4, c = id & 15;
        const void* src = g_Acat + (size_t)(m0 + row) * KCAT + gk + c * 8;
        cp_async16(ab + row * 256 + swz16(c, row), src);
    }
    uint32_t bb = sb + SM_B + stage * B_STAGE;
#pragma unroll
    for (int j = 0; j < 8; ++j) {            // B: 128 rows x 16 chunks = 2048
        int id = tid + j * 256;
        int row = id >> 4, c = id & 15;
        const void* src = g_Bcat + (size_t)(n0 + row) * KCAT + gk + c * 8;
        cp_async16(bb + row * 256 + swz16(c, row), src);
    }
    CP_COMMIT();
}

__device__ __forceinline__ void top2_upd(float& b1, int& i1, float& b2, int& i2,
                                         float s, int idx) {
    if (s > b1 || (s == b1 && idx < i1)) { b2 = b1; i2 = i1; b1 = s; i1 = idx; }
    else if (s > b2 || (s == b2 && idx < i2)) { b2 = s; i2 = idx; }
}

__global__ void __launch_bounds__(NTHR, 2)
vq_main_kernel() {
    extern __shared__ char smem[];
    uint32_t sb = smem_u32(smem);
    float*  e2s  = reinterpret_cast<float*>(smem + SM_E2);
    float4* mbuf = reinterpret_cast<float4*>(smem + SM_MBUF);

    const int tid  = threadIdx.x;
    const int lane = tid & 31;
    const int wid  = tid >> 5;
    const int wm   = wid >> 2;     // 0..1 (m half: 32 rows)
    const int wn   = wid & 3;      // 0..3 (n quarter: 32 cols)
    const int m0   = blockIdx.x * MT;

    float rb1 = -FLT_MAX, rb2 = -FLT_MAX;
    int   ri1 = 0x7fffffff, ri2 = 0x7fffffff;

    // Prologue: stage 0 of chunk 0. (Stage 1 is filled inside the k-loop.)
    fill_stage(sb, 0, 0, m0, 0, tid);

#pragma unroll 1
    for (int ch = 0; ch < NCHUNK; ++ch) {
        const int n0 = ch * BN;
        if (tid < BN) e2s[tid] = g_e2[n0 + tid];

        float acc[2][4][4];
#pragma unroll
        for (int a = 0; a < 2; ++a)
#pragma unroll
            for (int b = 0; b < 4; ++b)
#pragma unroll
                for (int c = 0; c < 4; ++c) acc[a][b][c] = 0.f;

#pragma unroll 1
        for (int st = 0; st < KSTEPS; ++st) {
            asm volatile("cp.async.wait_group 0;" ::: "memory");
            __syncthreads();
            // Refill the buffer freed by step st-1 (all warps are past it).
            if (st + 1 < KSTEPS)
                fill_stage(sb, (st + 1) & 1, st + 1, m0, n0, tid);
            else if (ch + 1 < NCHUNK)
                fill_stage(sb, 0, 0, m0, n0 + BN, tid);   // next chunk, stage 0

            const uint32_t ab = sb + SM_A + (st & 1) * A_STAGE;
            const uint32_t bb = sb + SM_B + (st & 1) * B_STAGE;

#pragma unroll
            for (int sub = 0; sub < 8; ++sub) {   // 8 x k16 per BK=128 step
                // ---- B fragments: 4 n-frags (8 cols each) = 2 ldmatrix.x4 ----
                uint32_t bfr[4][2];
#pragma unroll
                for (int p = 0; p < 2; ++p) {
                    int mi   = lane >> 3;          // 0..3
                    int noff = (mi >> 1) * 8;
                    int kc   = mi & 1;
                    int row  = wn * 32 + p * 16 + noff + (lane & 7);
                    int c    = sub * 2 + kc;
                    uint32_t addr = bb + row * 256 + swz16(c, row);
                    ldmatrix_x4(bfr[p*2][0], bfr[p*2][1],
                                bfr[p*2+1][0], bfr[p*2+1][1], addr);
                }
                // ---- A fragments + MMAs ----
#pragma unroll
                for (int mf = 0; mf < 2; ++mf) {
                    int row = wm * 32 + mf * 16 + (lane & 15);
                    int c   = sub * 2 + (lane >> 4);
                    uint32_t addr = ab + row * 256 + swz16(c, row);
                    uint32_t a0, a1, a2, a3;
                    ldmatrix_x4(a0, a1, a2, a3, addr);
#pragma unroll
                    for (int nf = 0; nf < 4; ++nf)
                        mma_bf16(acc[mf][nf][0], acc[mf][nf][1],
                                 acc[mf][nf][2], acc[mf][nf][3],
                                 a0, a1, a2, a3, bfr[nf][0], bfr[nf][1]);
                }
            }
        }
        __syncthreads();   // all HMMA smem reads of the last two stages done

        // Overlap: issue next chunk's stage-1 fill under the epilogue.
        if (ch + 1 < NCHUNK)
            fill_stage(sb, 1, 1, m0, n0 + BN, tid);

        // ---- epilogue: per-row top-2 over this chunk's 128 cols ----
        const int q = lane & 3;                    // col pair within frag
#pragma unroll
        for (int mf = 0; mf < 2; ++mf) {
#pragma unroll
            for (int h = 0; h < 2; ++h) {          // row half of the 16x8 frag
                float tb1 = -FLT_MAX, tb2 = -FLT_MAX;
                int   ti1 = 0x7fffffff, ti2 = 0x7fffffff;
#pragma unroll
                for (int nf = 0; nf < 4; ++nf) {
                    int cloc = wn * 32 + nf * 8 + q * 2;
                    float s0 = acc[mf][nf][h*2+0] - 0.5f * e2s[cloc];
                    float s1 = acc[mf][nf][h*2+1] - 0.5f * e2s[cloc+1];
                    top2_upd(tb1, ti1, tb2, ti2, s0, n0 + cloc);
                    top2_upd(tb1, ti1, tb2, ti2, s1, n0 + cloc + 1);
                }
                // quad merge (lanes differing in bits 0,1 share the row)
#pragma unroll
                for (int o = 1; o <= 2; o <<= 1) {
                    float ob1 = __shfl_xor_sync(0xffffffffu, tb1, o);
                    float ob2 = __shfl_xor_sync(0xffffffffu, tb2, o);
                    int   oi1 = __shfl_xor_sync(0xffffffffu, ti1, o);
                    int   oi2 = __shfl_xor_sync(0xffffffffu, ti2, o);
                    top2_upd(tb1, ti1, tb2, ti2, ob1, oi1);
                    top2_upd(tb1, ti1, tb2, ti2, ob2, oi2);
                }
                if (q == 0) {
                    int row_local = wm * 32 + mf * 16 + h * 8 + (lane >> 2);
                    mbuf[row_local * 4 + wn] =
                        make_float4(tb1, tb2, __int_as_float(ti1), __int_as_float(ti2));
                }
            }
        }
        __syncthreads();
        if (tid < MT) {
#pragma unroll
            for (int w = 0; w < 4; ++w) {
                float4 v = mbuf[tid * 4 + w];
                top2_upd(rb1, ri1, rb2, ri2, v.x, __float_as_int(v.z));
                top2_upd(rb1, ri1, rb2, ri2, v.y, __float_as_int(v.w));
            }
        }
        __syncthreads();   // protect e2s/mbuf before next chunk rewrites
    }

    if (tid < MT) { g_i1[m0 + tid] = ri1; g_i2[m0 + tid] = ri2; }
}

// ---------------------------------------------------------------------------
// Refine + gather: exact fp32 re-score of top-2, copy the winner row.
// ---------------------------------------------------------------------------
__global__ void refine_gather_kernel(const float* __restrict__ x,
                                     const float* __restrict__ emb,
                                     float* __restrict__ out) {
    int row  = (blockIdx.x * blockDim.x + threadIdx.x) >> 5;
    int lane = threadIdx.x & 31;
    int i1 = g_i1[row], i2 = g_i2[row];

    const float4* xr = reinterpret_cast<const float4*>(x + (size_t)row * DIM);
    const float4* e1 = reinterpret_cast<const float4*>(emb + (size_t)i1 * DIM);
    const float4* e2 = reinterpret_cast<const float4*>(emb + (size_t)i2 * DIM);
    float d1 = 0.f, d2 = 0.f;
#pragma unroll
    for (int j = 0; j < 4; ++j) {
        float4 xv = xr[lane + j * 32];
        float4 a  = e1[lane + j * 32];
        float4 b  = e2[lane + j * 32];
        d1 += xv.x * a.x + xv.y * a.y + xv.z * a.z + xv.w * a.w;
        d2 += xv.x * b.x + xv.y * b.y + xv.z * b.z + xv.w * b.w;
    }
#pragma unroll
    for (int o = 16; o; o >>= 1) {
        d1 += __shfl_xor_sync(0xffffffffu, d1, o);
        d2 += __shfl_xor_sync(0xffffffffu, d2, o);
    }
    float s1 = d1 - 0.5f * g_e2[i1];
    float s2 = d2 - 0.5f * g_e2[i2];
    int best = (s2 > s1 || (s2 == s1 && i2 < i1)) ? i2 : i1;

    const float4* src = reinterpret_cast<const float4*>(emb + (size_t)best * DIM);
    float4*       dst = reinterpret_cast<float4*>(out + (size_t)row * DIM);
#pragma unroll
    for (int j = 0; j < 4; ++j) dst[lane + j * 32] = src[lane + j * 32];
}

// ---------------------------------------------------------------------------
extern "C" void kernel_launch(void* const* d_in, const int* in_sizes, int n_in,
                              void* d_out, int out_size) {
    const float* x   = (const float*)d_in[0];
    const float* emb = (const float*)d_in[1];
    float*       out = (float*)d_out;

    cudaFuncSetAttribute(vq_main_kernel,
                         cudaFuncAttributeMaxDynamicSharedMemorySize, SMEM_TOTAL);

    e2_kernel<<<K_CODES / 8, 256>>>(emb);
    split_x_kernel<<<(M_TOTAL * DIM) / 256, 256>>>(x);
    split_e_kernel<<<(K_CODES * DIM) / 256, 256>>>(emb);
    vq_main_kernel<<<M_TOTAL / MT, NTHR, SMEM_TOTAL>>>();
    refine_gather_kernel<<<M_TOTAL / 8, 256>>>(x, emb, out);
}